// round 12
// baseline (speedup 1.0000x reference)
#include <cuda_runtime.h>
#include <cstdint>

// ---------------- problem constants (fixed by dataset) ----------------
#define MAXN 100000
#define MAXE 1600000
#define FIN  128
#define HID  64
#define FOUT 32

// ---------------- device scratch (static: no allocs allowed) ----------
__device__ float g_ha[MAXN * HID];        // GEMM output / agg input
__device__ float g_hb[MAXN * HID];        // agg output (relu'd)
__device__ int   g_src[MAXE];
__device__ int   g_dst[MAXE];
__device__ int   g_csr_src[MAXE];
__device__ float g_csr_norm[MAXE];
__device__ float g_deg[MAXN];
__device__ float g_dinv[MAXN];
__device__ int   g_cnt[MAXN];
__device__ int   g_fill[MAXN];
__device__ int   g_rowptr[MAXN + 1];
__device__ float g_pool[256 * FOUT];
__device__ int   g_flag;                  // 1 if edge_index is int64 layout

// ---------------- dtype detection for edge_index ----------------------
// If the buffer is int64 (values < 2^31, nonneg), every odd int32 word is 0.
// If it is int32 edge data, odd words are random node ids (~never all zero).
__global__ void detect_kernel(const int* __restrict__ ei32) {
    if (threadIdx.x == 0 && blockIdx.x == 0) {
        int zeros = 0;
        for (int i = 0; i < 256; i++)
            if (ei32[2 * i + 1] == 0) zeros++;
        g_flag = (zeros == 256) ? 1 : 0;
    }
}

// ---------------- init ------------------------------------------------
__global__ void init_kernel(int N) {
    int i = blockIdx.x * blockDim.x + threadIdx.x;
    if (i < N) {
        g_deg[i] = 1.0f;   // self-loop weight
        g_cnt[i] = 0;
        g_fill[i] = 0;
    }
}

// ---------------- pass 1: degree + counts + int32 conversion ----------
__global__ void edge_pass_kernel(const void* __restrict__ eidx,
                                 const float* __restrict__ ew, int E) {
    int e = blockIdx.x * blockDim.x + threadIdx.x;
    if (e >= E) return;
    int s, d;
    if (g_flag) {
        const long long* p = (const long long*)eidx;
        s = (int)p[e];
        d = (int)p[E + e];
    } else {
        const int* p = (const int*)eidx;
        s = p[e];
        d = p[E + e];
    }
    g_src[e] = s;
    g_dst[e] = d;
    atomicAdd(&g_deg[d], ew[e]);
    atomicAdd(&g_cnt[d], 1);
}

__global__ void dinv_kernel(int N) {
    int i = blockIdx.x * blockDim.x + threadIdx.x;
    if (i < N) {
        float dg = g_deg[i];
        g_dinv[i] = (dg > 0.0f) ? rsqrtf(dg) : 0.0f;
    }
}

// ---------------- exclusive scan of g_cnt -> g_rowptr ------------------
// single block, 1024 threads, 4 elems/thread per chunk, warp-shuffle scans.
__global__ void scan_kernel(int N) {
    __shared__ int sh[32];
    int tid = threadIdx.x;
    int lane = tid & 31, wid = tid >> 5;
    int carry = 0;
    const int CH = 4096;
    for (int base = 0; base < N; base += CH) {
        int idx = base + tid * 4;
        int v0 = (idx + 0 < N) ? g_cnt[idx + 0] : 0;
        int v1 = (idx + 1 < N) ? g_cnt[idx + 1] : 0;
        int v2 = (idx + 2 < N) ? g_cnt[idx + 2] : 0;
        int v3 = (idx + 3 < N) ? g_cnt[idx + 3] : 0;
        int p0 = v0, p1 = p0 + v1, p2 = p1 + v2, p3 = p2 + v3;
        int t = p3;
        #pragma unroll
        for (int o = 1; o < 32; o <<= 1) {
            int u = __shfl_up_sync(0xFFFFFFFFu, t, o);
            if (lane >= o) t += u;
        }
        if (lane == 31) sh[wid] = t;
        __syncthreads();
        if (wid == 0) {
            int s = sh[lane];
            #pragma unroll
            for (int o = 1; o < 32; o <<= 1) {
                int u = __shfl_up_sync(0xFFFFFFFFu, s, o);
                if (lane >= o) s += u;
            }
            sh[lane] = s;
        }
        __syncthreads();
        int woff = (wid > 0) ? sh[wid - 1] : 0;
        int off = carry + woff + (t - p3);   // exclusive base for this thread
        if (idx + 0 < N) g_rowptr[idx + 0] = off;
        if (idx + 1 < N) g_rowptr[idx + 1] = off + p0;
        if (idx + 2 < N) g_rowptr[idx + 2] = off + p1;
        if (idx + 3 < N) g_rowptr[idx + 3] = off + p2;
        int total = sh[31];
        __syncthreads();
        carry += total;
    }
    if (tid == 0) g_rowptr[N] = carry;
}

// ---------------- pass 2: CSR fill (bucket order irrelevant) ----------
__global__ void fill_kernel(const float* __restrict__ ew, int E) {
    int e = blockIdx.x * blockDim.x + threadIdx.x;
    if (e >= E) return;
    int s = g_src[e];
    int d = g_dst[e];
    int pos = g_rowptr[d] + atomicAdd(&g_fill[d], 1);
    g_csr_src[pos] = s;
    g_csr_norm[pos] = g_dinv[s] * ew[e] * g_dinv[d];
}

// ---------------- fp32 SGEMM: C[N,NOUT] = A[N,K] @ W[K,NOUT] -----------
// BM=128 rows/block, 256 threads, thread tile TM x 4, K chunked by 16.
template <int K, int NOUT, int TM>
__global__ __launch_bounds__(256) void gemm_kernel(
    const float* __restrict__ A, const float* __restrict__ W,
    float* __restrict__ C, int N) {
    constexpr int BM = 128, TN = 4, KC = 16;
    constexpr int NCOL = NOUT / TN;
    __shared__ float xs[KC][BM];
    __shared__ float ws[KC][NOUT];
    int tid = threadIdx.x;
    int tcol = tid % NCOL, trow = tid / NCOL;
    int r0 = blockIdx.x * BM;
    int lrow = tid >> 1, half = tid & 1;

    float acc[TM][TN];
    #pragma unroll
    for (int i = 0; i < TM; i++)
        #pragma unroll
        for (int j = 0; j < TN; j++) acc[i][j] = 0.0f;

    for (int k0 = 0; k0 < K; k0 += KC) {
        // load A tile transposed: xs[kk][row]
        int grow = r0 + lrow;
        float4 u0 = make_float4(0, 0, 0, 0), u1 = make_float4(0, 0, 0, 0);
        if (grow < N) {
            const float4* xp =
                (const float4*)(A + (size_t)grow * K + k0 + half * 8);
            u0 = xp[0];
            u1 = xp[1];
        }
        int kb = half * 8;
        xs[kb + 0][lrow] = u0.x; xs[kb + 1][lrow] = u0.y;
        xs[kb + 2][lrow] = u0.z; xs[kb + 3][lrow] = u0.w;
        xs[kb + 4][lrow] = u1.x; xs[kb + 5][lrow] = u1.y;
        xs[kb + 6][lrow] = u1.z; xs[kb + 7][lrow] = u1.w;
        // load W tile
        constexpr int NF4 = KC * NOUT / 4;
        if (tid < NF4) {
            int kk = tid / (NOUT / 4);
            int c = (tid % (NOUT / 4)) * 4;
            *(float4*)&ws[kk][c] =
                *(const float4*)(W + (size_t)(k0 + kk) * NOUT + c);
        }
        __syncthreads();
        #pragma unroll
        for (int kk = 0; kk < KC; kk++) {
            float4 b4 = *(float4*)&ws[kk][tcol * TN];
            float a[TM];
            #pragma unroll
            for (int i = 0; i < TM; i += 4) {
                float4 a4 = *(float4*)&xs[kk][trow * TM + i];
                a[i] = a4.x; a[i + 1] = a4.y; a[i + 2] = a4.z; a[i + 3] = a4.w;
            }
            #pragma unroll
            for (int i = 0; i < TM; i++) {
                acc[i][0] += a[i] * b4.x;
                acc[i][1] += a[i] * b4.y;
                acc[i][2] += a[i] * b4.z;
                acc[i][3] += a[i] * b4.w;
            }
        }
        __syncthreads();
    }
    #pragma unroll
    for (int i = 0; i < TM; i++) {
        int grow = r0 + trow * TM + i;
        if (grow < N) {
            *(float4*)(C + (size_t)grow * NOUT + tcol * TN) =
                make_float4(acc[i][0], acc[i][1], acc[i][2], acc[i][3]);
        }
    }
}

// ---------------- aggregation: out[i] = relu?(sum_e norm*h[src] + self + b)
// one warp per node; NF=64 -> float2/lane, NF=32 -> float/lane.
// 4-deep MLP unroll to hide L2 latency.
template <int NF, bool RELU>
__global__ __launch_bounds__(256) void agg_kernel(
    const float* __restrict__ h, const float* __restrict__ bias,
    float* __restrict__ out, int N) {
    int warp = (blockIdx.x * blockDim.x + threadIdx.x) >> 5;
    int lane = threadIdx.x & 31;
    if (warp >= N) return;
    constexpr int FPL = NF / 32;
    float di = g_dinv[warp];
    float sw = di * di;

    float acc0, acc1 = 0.0f;
    const float* hrow = h + (size_t)warp * NF + lane * FPL;
    if (FPL == 2) {
        float2 v = *(const float2*)hrow;
        acc0 = sw * v.x;
        acc1 = sw * v.y;
    } else {
        acc0 = sw * hrow[0];
    }

    int e = g_rowptr[warp];
    int end = g_rowptr[warp + 1];
    for (; e + 4 <= end; e += 4) {
        int s0 = g_csr_src[e + 0], s1 = g_csr_src[e + 1];
        int s2 = g_csr_src[e + 2], s3 = g_csr_src[e + 3];
        float w0 = g_csr_norm[e + 0], w1 = g_csr_norm[e + 1];
        float w2 = g_csr_norm[e + 2], w3 = g_csr_norm[e + 3];
        if (FPL == 2) {
            float2 v0 = *(const float2*)(h + (size_t)s0 * NF + lane * 2);
            float2 v1 = *(const float2*)(h + (size_t)s1 * NF + lane * 2);
            float2 v2 = *(const float2*)(h + (size_t)s2 * NF + lane * 2);
            float2 v3 = *(const float2*)(h + (size_t)s3 * NF + lane * 2);
            acc0 += w0 * v0.x; acc1 += w0 * v0.y;
            acc0 += w1 * v1.x; acc1 += w1 * v1.y;
            acc0 += w2 * v2.x; acc1 += w2 * v2.y;
            acc0 += w3 * v3.x; acc1 += w3 * v3.y;
        } else {
            float v0 = h[(size_t)s0 * NF + lane];
            float v1 = h[(size_t)s1 * NF + lane];
            float v2 = h[(size_t)s2 * NF + lane];
            float v3 = h[(size_t)s3 * NF + lane];
            acc0 += w0 * v0 + w1 * v1 + w2 * v2 + w3 * v3;
        }
    }
    for (; e < end; e++) {
        int s = g_csr_src[e];
        float w = g_csr_norm[e];
        if (FPL == 2) {
            float2 v = *(const float2*)(h + (size_t)s * NF + lane * 2);
            acc0 += w * v.x;
            acc1 += w * v.y;
        } else {
            acc0 += w * h[(size_t)s * NF + lane];
        }
    }

    float* orow = out + (size_t)warp * NF + lane * FPL;
    if (FPL == 2) {
        float r0 = acc0 + bias[lane * 2 + 0];
        float r1 = acc1 + bias[lane * 2 + 1];
        if (RELU) { r0 = fmaxf(r0, 0.0f); r1 = fmaxf(r1, 0.0f); }
        float2 r; r.x = r0; r.y = r1;
        *(float2*)orow = r;
    } else {
        float r0 = acc0 + bias[lane];
        if (RELU) r0 = fmaxf(r0, 0.0f);
        orow[0] = r0;
    }
}

// ---------------- mean pool over node embeddings -----------------------
__global__ void pool1_kernel(const float* __restrict__ emb, int N) {
    __shared__ float sh[256];
    int tid = threadIdx.x;
    int g = blockIdx.x * 256 + tid;
    const int G = 256 * 256;           // G % 32 == 0 -> feature is g % 32
    float s = 0.0f;
    int total = N * FOUT;
    for (int i = g; i < total; i += G) s += emb[i];
    sh[tid] = s;
    __syncthreads();
    if (tid < FOUT) {
        float t = 0.0f;
        #pragma unroll
        for (int j = 0; j < 256 / FOUT; j++) t += sh[tid + j * FOUT];
        g_pool[blockIdx.x * FOUT + tid] = t;
    }
}

__global__ void pool2_kernel(float* __restrict__ out, int N) {
    int f = threadIdx.x;
    if (f < FOUT) {
        float s = 0.0f;
        for (int b = 0; b < 256; b++) s += g_pool[b * FOUT + f];
        out[(size_t)N * FOUT + f] = s / (float)N;
    }
}

// ---------------- launch ------------------------------------------------
static inline int cdiv(int a, int b) { return (a + b - 1) / b; }

extern "C" void kernel_launch(void* const* d_in, const int* in_sizes, int n_in,
                              void* d_out, int out_size) {
    const float* x  = (const float*)d_in[0];
    const void*  ei = d_in[1];
    const float* ew = (const float*)d_in[2];
    const float* W1 = (const float*)d_in[3];
    const float* b1 = (const float*)d_in[4];
    const float* W2 = (const float*)d_in[5];
    const float* b2 = (const float*)d_in[6];
    const float* W3 = (const float*)d_in[7];
    const float* b3 = (const float*)d_in[8];
    float* out = (float*)d_out;

    int E = in_sizes[2];
    int N = in_sizes[0] / FIN;
    if (N > MAXN) N = MAXN;
    if (E > MAXE) E = MAXE;

    float *p_ha, *p_hb;
    cudaGetSymbolAddress((void**)&p_ha, g_ha);
    cudaGetSymbolAddress((void**)&p_hb, g_hb);

    // ---- preprocessing: norm + CSR ----
    detect_kernel<<<1, 32>>>((const int*)ei);
    init_kernel<<<cdiv(N, 256), 256>>>(N);
    edge_pass_kernel<<<cdiv(E, 256), 256>>>(ei, ew, E);
    dinv_kernel<<<cdiv(N, 256), 256>>>(N);
    scan_kernel<<<1, 1024>>>(N);
    fill_kernel<<<cdiv(E, 256), 256>>>(ew, E);

    int gemm_blocks = cdiv(N, 128);
    int agg_blocks = cdiv(N, 8);      // 8 warps per 256-thread block

    // ---- layer 1 ----
    gemm_kernel<FIN, HID, 8><<<gemm_blocks, 256>>>(x, W1, p_ha, N);
    agg_kernel<HID, true><<<agg_blocks, 256>>>(p_ha, b1, p_hb, N);
    // ---- layer 2 ----
    gemm_kernel<HID, HID, 8><<<gemm_blocks, 256>>>(p_hb, W2, p_ha, N);
    agg_kernel<HID, true><<<agg_blocks, 256>>>(p_ha, b2, p_hb, N);
    // ---- layer 3 ----
    gemm_kernel<HID, FOUT, 4><<<gemm_blocks, 256>>>(p_hb, W3, p_ha, N);
    agg_kernel<FOUT, false><<<agg_blocks, 256>>>(p_ha, b3, out, N);

    // ---- mean pool (only if d_out has room for the graph embedding) ----
    if (out_size >= N * FOUT + FOUT) {
        pool1_kernel<<<256, 256>>>(out, N);
        pool2_kernel<<<1, 32>>>(out, N);
    }
}

// round 13
// speedup vs baseline: 1.0065x; 1.0065x over previous
#include <cuda_runtime.h>
#include <cstdint>

// ---------------- problem constants (fixed by dataset) ----------------
#define MAXN 100000
#define MAXE 1600000
#define FIN  128
#define HID  64
#define FOUT 32

// ---------------- device scratch (static: no allocs allowed) ----------
__device__ float g_ha[MAXN * HID];        // GEMM output / agg input
__device__ float g_hb[MAXN * HID];        // agg output (relu'd)
__device__ int   g_src[MAXE];
__device__ int   g_dst[MAXE];
__device__ int   g_csr_src[MAXE];
__device__ float g_csr_norm[MAXE];
__device__ float g_deg[MAXN];
__device__ float g_dinv[MAXN];
__device__ int   g_cnt[MAXN];
__device__ int   g_fill[MAXN];
__device__ int   g_rowptr[MAXN + 1];
__device__ float g_pool[256 * FOUT];
__device__ int   g_flag;                  // 1 if edge_index is int64 layout

// ---------------- dtype detection for edge_index ----------------------
// If the buffer is int64 (values < 2^31, nonneg), every odd int32 word is 0.
// If it is int32 edge data, odd words are random node ids (~never all zero).
__global__ void detect_kernel(const int* __restrict__ ei32) {
    if (threadIdx.x == 0 && blockIdx.x == 0) {
        int zeros = 0;
        for (int i = 0; i < 256; i++)
            if (ei32[2 * i + 1] == 0) zeros++;
        g_flag = (zeros == 256) ? 1 : 0;
    }
}

// ---------------- init ------------------------------------------------
__global__ void init_kernel(int N) {
    int i = blockIdx.x * blockDim.x + threadIdx.x;
    if (i < N) {
        g_deg[i] = 1.0f;   // self-loop weight
        g_cnt[i] = 0;
        g_fill[i] = 0;
    }
}

// ---------------- pass 1: degree + counts + int32 conversion ----------
__global__ void edge_pass_kernel(const void* __restrict__ eidx,
                                 const float* __restrict__ ew, int E) {
    int e = blockIdx.x * blockDim.x + threadIdx.x;
    if (e >= E) return;
    int s, d;
    if (g_flag) {
        const long long* p = (const long long*)eidx;
        s = (int)p[e];
        d = (int)p[E + e];
    } else {
        const int* p = (const int*)eidx;
        s = p[e];
        d = p[E + e];
    }
    g_src[e] = s;
    g_dst[e] = d;
    atomicAdd(&g_deg[d], ew[e]);
    atomicAdd(&g_cnt[d], 1);
}

__global__ void dinv_kernel(int N) {
    int i = blockIdx.x * blockDim.x + threadIdx.x;
    if (i < N) {
        float dg = g_deg[i];
        g_dinv[i] = (dg > 0.0f) ? rsqrtf(dg) : 0.0f;
    }
}

// ---------------- exclusive scan of g_cnt -> g_rowptr ------------------
// single block, 1024 threads, 4 elems/thread per chunk, warp-shuffle scans.
__global__ void scan_kernel(int N) {
    __shared__ int sh[32];
    int tid = threadIdx.x;
    int lane = tid & 31, wid = tid >> 5;
    int carry = 0;
    const int CH = 4096;
    for (int base = 0; base < N; base += CH) {
        int idx = base + tid * 4;
        int v0 = (idx + 0 < N) ? g_cnt[idx + 0] : 0;
        int v1 = (idx + 1 < N) ? g_cnt[idx + 1] : 0;
        int v2 = (idx + 2 < N) ? g_cnt[idx + 2] : 0;
        int v3 = (idx + 3 < N) ? g_cnt[idx + 3] : 0;
        int p0 = v0, p1 = p0 + v1, p2 = p1 + v2, p3 = p2 + v3;
        int t = p3;
        #pragma unroll
        for (int o = 1; o < 32; o <<= 1) {
            int u = __shfl_up_sync(0xFFFFFFFFu, t, o);
            if (lane >= o) t += u;
        }
        if (lane == 31) sh[wid] = t;
        __syncthreads();
        if (wid == 0) {
            int s = sh[lane];
            #pragma unroll
            for (int o = 1; o < 32; o <<= 1) {
                int u = __shfl_up_sync(0xFFFFFFFFu, s, o);
                if (lane >= o) s += u;
            }
            sh[lane] = s;
        }
        __syncthreads();
        int woff = (wid > 0) ? sh[wid - 1] : 0;
        int off = carry + woff + (t - p3);   // exclusive base for this thread
        if (idx + 0 < N) g_rowptr[idx + 0] = off;
        if (idx + 1 < N) g_rowptr[idx + 1] = off + p0;
        if (idx + 2 < N) g_rowptr[idx + 2] = off + p1;
        if (idx + 3 < N) g_rowptr[idx + 3] = off + p2;
        int total = sh[31];
        __syncthreads();
        carry += total;
    }
    if (tid == 0) g_rowptr[N] = carry;
}

// ---------------- pass 2: CSR fill (bucket order irrelevant) ----------
__global__ void fill_kernel(const float* __restrict__ ew, int E) {
    int e = blockIdx.x * blockDim.x + threadIdx.x;
    if (e >= E) return;
    int s = g_src[e];
    int d = g_dst[e];
    int pos = g_rowptr[d] + atomicAdd(&g_fill[d], 1);
    g_csr_src[pos] = s;
    g_csr_norm[pos] = g_dinv[s] * ew[e] * g_dinv[d];
}

// ---------------- fp32 SGEMM: C[N,NOUT] = A[N,K] @ W[K,NOUT] -----------
// BM=128 rows/block, 256 threads, thread tile TM x 4, K chunked by 16.
template <int K, int NOUT, int TM>
__global__ __launch_bounds__(256) void gemm_kernel(
    const float* __restrict__ A, const float* __restrict__ W,
    float* __restrict__ C, int N) {
    constexpr int BM = 128, TN = 4, KC = 16;
    constexpr int NCOL = NOUT / TN;
    __shared__ float xs[KC][BM];
    __shared__ float ws[KC][NOUT];
    int tid = threadIdx.x;
    int tcol = tid % NCOL, trow = tid / NCOL;
    int r0 = blockIdx.x * BM;
    int lrow = tid >> 1, half = tid & 1;

    float acc[TM][TN];
    #pragma unroll
    for (int i = 0; i < TM; i++)
        #pragma unroll
        for (int j = 0; j < TN; j++) acc[i][j] = 0.0f;

    for (int k0 = 0; k0 < K; k0 += KC) {
        // load A tile transposed: xs[kk][row]
        int grow = r0 + lrow;
        float4 u0 = make_float4(0, 0, 0, 0), u1 = make_float4(0, 0, 0, 0);
        if (grow < N) {
            const float4* xp =
                (const float4*)(A + (size_t)grow * K + k0 + half * 8);
            u0 = xp[0];
            u1 = xp[1];
        }
        int kb = half * 8;
        xs[kb + 0][lrow] = u0.x; xs[kb + 1][lrow] = u0.y;
        xs[kb + 2][lrow] = u0.z; xs[kb + 3][lrow] = u0.w;
        xs[kb + 4][lrow] = u1.x; xs[kb + 5][lrow] = u1.y;
        xs[kb + 6][lrow] = u1.z; xs[kb + 7][lrow] = u1.w;
        // load W tile
        constexpr int NF4 = KC * NOUT / 4;
        if (tid < NF4) {
            int kk = tid / (NOUT / 4);
            int c = (tid % (NOUT / 4)) * 4;
            *(float4*)&ws[kk][c] =
                *(const float4*)(W + (size_t)(k0 + kk) * NOUT + c);
        }
        __syncthreads();
        #pragma unroll
        for (int kk = 0; kk < KC; kk++) {
            float4 b4 = *(float4*)&ws[kk][tcol * TN];
            float a[TM];
            #pragma unroll
            for (int i = 0; i < TM; i += 4) {
                float4 a4 = *(float4*)&xs[kk][trow * TM + i];
                a[i] = a4.x; a[i + 1] = a4.y; a[i + 2] = a4.z; a[i + 3] = a4.w;
            }
            #pragma unroll
            for (int i = 0; i < TM; i++) {
                acc[i][0] += a[i] * b4.x;
                acc[i][1] += a[i] * b4.y;
                acc[i][2] += a[i] * b4.z;
                acc[i][3] += a[i] * b4.w;
            }
        }
        __syncthreads();
    }
    #pragma unroll
    for (int i = 0; i < TM; i++) {
        int grow = r0 + trow * TM + i;
        if (grow < N) {
            *(float4*)(C + (size_t)grow * NOUT + tcol * TN) =
                make_float4(acc[i][0], acc[i][1], acc[i][2], acc[i][3]);
        }
    }
}

// ---------------- aggregation: out[i] = relu?(sum_e norm*h[src] + self + b)
// one warp per node; NF=64 -> float2/lane, NF=32 -> float/lane.
// 4-deep MLP unroll to hide L2 latency.
template <int NF, bool RELU>
__global__ __launch_bounds__(256) void agg_kernel(
    const float* __restrict__ h, const float* __restrict__ bias,
    float* __restrict__ out, int N) {
    int warp = (blockIdx.x * blockDim.x + threadIdx.x) >> 5;
    int lane = threadIdx.x & 31;
    if (warp >= N) return;
    constexpr int FPL = NF / 32;
    float di = g_dinv[warp];
    float sw = di * di;

    float acc0, acc1 = 0.0f;
    const float* hrow = h + (size_t)warp * NF + lane * FPL;
    if (FPL == 2) {
        float2 v = *(const float2*)hrow;
        acc0 = sw * v.x;
        acc1 = sw * v.y;
    } else {
        acc0 = sw * hrow[0];
    }

    int e = g_rowptr[warp];
    int end = g_rowptr[warp + 1];
    for (; e + 4 <= end; e += 4) {
        int s0 = g_csr_src[e + 0], s1 = g_csr_src[e + 1];
        int s2 = g_csr_src[e + 2], s3 = g_csr_src[e + 3];
        float w0 = g_csr_norm[e + 0], w1 = g_csr_norm[e + 1];
        float w2 = g_csr_norm[e + 2], w3 = g_csr_norm[e + 3];
        if (FPL == 2) {
            float2 v0 = *(const float2*)(h + (size_t)s0 * NF + lane * 2);
            float2 v1 = *(const float2*)(h + (size_t)s1 * NF + lane * 2);
            float2 v2 = *(const float2*)(h + (size_t)s2 * NF + lane * 2);
            float2 v3 = *(const float2*)(h + (size_t)s3 * NF + lane * 2);
            acc0 += w0 * v0.x; acc1 += w0 * v0.y;
            acc0 += w1 * v1.x; acc1 += w1 * v1.y;
            acc0 += w2 * v2.x; acc1 += w2 * v2.y;
            acc0 += w3 * v3.x; acc1 += w3 * v3.y;
        } else {
            float v0 = h[(size_t)s0 * NF + lane];
            float v1 = h[(size_t)s1 * NF + lane];
            float v2 = h[(size_t)s2 * NF + lane];
            float v3 = h[(size_t)s3 * NF + lane];
            acc0 += w0 * v0 + w1 * v1 + w2 * v2 + w3 * v3;
        }
    }
    for (; e < end; e++) {
        int s = g_csr_src[e];
        float w = g_csr_norm[e];
        if (FPL == 2) {
            float2 v = *(const float2*)(h + (size_t)s * NF + lane * 2);
            acc0 += w * v.x;
            acc1 += w * v.y;
        } else {
            acc0 += w * h[(size_t)s * NF + lane];
        }
    }

    float* orow = out + (size_t)warp * NF + lane * FPL;
    if (FPL == 2) {
        float r0 = acc0 + bias[lane * 2 + 0];
        float r1 = acc1 + bias[lane * 2 + 1];
        if (RELU) { r0 = fmaxf(r0, 0.0f); r1 = fmaxf(r1, 0.0f); }
        float2 r; r.x = r0; r.y = r1;
        *(float2*)orow = r;
    } else {
        float r0 = acc0 + bias[lane];
        if (RELU) r0 = fmaxf(r0, 0.0f);
        orow[0] = r0;
    }
}

// ---------------- mean pool over node embeddings -----------------------
__global__ void pool1_kernel(const float* __restrict__ emb, int N) {
    __shared__ float sh[256];
    int tid = threadIdx.x;
    int g = blockIdx.x * 256 + tid;
    const int G = 256 * 256;           // G % 32 == 0 -> feature is g % 32
    float s = 0.0f;
    int total = N * FOUT;
    for (int i = g; i < total; i += G) s += emb[i];
    sh[tid] = s;
    __syncthreads();
    if (tid < FOUT) {
        float t = 0.0f;
        #pragma unroll
        for (int j = 0; j < 256 / FOUT; j++) t += sh[tid + j * FOUT];
        g_pool[blockIdx.x * FOUT + tid] = t;
    }
}

__global__ void pool2_kernel(float* __restrict__ out, int N) {
    int f = threadIdx.x;
    if (f < FOUT) {
        float s = 0.0f;
        for (int b = 0; b < 256; b++) s += g_pool[b * FOUT + f];
        out[(size_t)N * FOUT + f] = s / (float)N;
    }
}

// ---------------- launch ------------------------------------------------
static inline int cdiv(int a, int b) { return (a + b - 1) / b; }

extern "C" void kernel_launch(void* const* d_in, const int* in_sizes, int n_in,
                              void* d_out, int out_size) {
    const float* x  = (const float*)d_in[0];
    const void*  ei = d_in[1];
    const float* ew = (const float*)d_in[2];
    const float* W1 = (const float*)d_in[3];
    const float* b1 = (const float*)d_in[4];
    const float* W2 = (const float*)d_in[5];
    const float* b2 = (const float*)d_in[6];
    const float* W3 = (const float*)d_in[7];
    const float* b3 = (const float*)d_in[8];
    float* out = (float*)d_out;

    int E = in_sizes[2];
    int N = in_sizes[0] / FIN;
    if (N > MAXN) N = MAXN;
    if (E > MAXE) E = MAXE;

    float *p_ha, *p_hb;
    cudaGetSymbolAddress((void**)&p_ha, g_ha);
    cudaGetSymbolAddress((void**)&p_hb, g_hb);

    // ---- preprocessing: norm + CSR ----
    detect_kernel<<<1, 32>>>((const int*)ei);
    init_kernel<<<cdiv(N, 256), 256>>>(N);
    edge_pass_kernel<<<cdiv(E, 256), 256>>>(ei, ew, E);
    dinv_kernel<<<cdiv(N, 256), 256>>>(N);
    scan_kernel<<<1, 1024>>>(N);
    fill_kernel<<<cdiv(E, 256), 256>>>(ew, E);

    int gemm_blocks = cdiv(N, 128);
    int agg_blocks = cdiv(N, 8);      // 8 warps per 256-thread block

    // ---- layer 1 ----
    gemm_kernel<FIN, HID, 8><<<gemm_blocks, 256>>>(x, W1, p_ha, N);
    agg_kernel<HID, true><<<agg_blocks, 256>>>(p_ha, b1, p_hb, N);
    // ---- layer 2 ----
    gemm_kernel<HID, HID, 8><<<gemm_blocks, 256>>>(p_hb, W2, p_ha, N);
    agg_kernel<HID, true><<<agg_blocks, 256>>>(p_ha, b2, p_hb, N);
    // ---- layer 3 ----
    gemm_kernel<HID, FOUT, 4><<<gemm_blocks, 256>>>(p_hb, W3, p_ha, N);
    agg_kernel<FOUT, false><<<agg_blocks, 256>>>(p_ha, b3, out, N);

    // ---- mean pool (only if d_out has room for the graph embedding) ----
    if (out_size >= N * FOUT + FOUT) {
        pool1_kernel<<<256, 256>>>(out, N);
        pool2_kernel<<<1, 32>>>(out, N);
    }
}

// round 14
// speedup vs baseline: 1.0615x; 1.0546x over previous
#include <cuda_runtime.h>
#include <cstdint>

// ---------------- problem constants (fixed by dataset) ----------------
#define MAXN 100000
#define MAXE 1600000
#define FIN  128
#define HID  64
#define FOUT 32

// ---------------- device scratch (static: no allocs allowed) ----------
__device__ float g_ha[MAXN * HID];        // GEMM output / agg input
__device__ float g_hb[MAXN * HID];        // agg output (relu'd)
__device__ int2  g_edge[MAXE];            // (src, dst)
__device__ int2  g_csr[MAXE];             // (src, norm-as-bits) packed
__device__ float g_deg[MAXN];
__device__ int   g_cnt[MAXN];
__device__ int   g_fill[MAXN];
__device__ int   g_rowptr[MAXN + 1];
__device__ float g_pool_acc[FOUT];
__device__ int   g_flag;                  // 1 if edge_index is int64 layout

static inline int cdiv(int a, int b) { return (a + b - 1) / b; }

// ---------------- setup: init + pool zero + dtype detect --------------
// int64 detection: values < 2^31 nonneg -> every odd int32 word is 0.
__global__ void setup_kernel(const int* __restrict__ ei32, int N) {
    int i = blockIdx.x * blockDim.x + threadIdx.x;
    if (i < N) {
        g_deg[i] = 1.0f;   // self-loop weight
        g_cnt[i] = 0;
        g_fill[i] = 0;
    }
    if (blockIdx.x == 0 && threadIdx.x < 32) {
        g_pool_acc[threadIdx.x] = 0.0f;
        bool z = true;
        #pragma unroll
        for (int j = 0; j < 8; j++)
            z = z && (ei32[2 * (threadIdx.x * 8 + j) + 1] == 0);
        unsigned m = __ballot_sync(0xFFFFFFFFu, z);
        if (threadIdx.x == 0) g_flag = (m == 0xFFFFFFFFu) ? 1 : 0;
    }
}

// ---------------- pass 1: degree + counts + edge conversion -----------
__global__ void edge_pass_kernel(const void* __restrict__ eidx,
                                 const float* __restrict__ ew, int E) {
    int e = blockIdx.x * blockDim.x + threadIdx.x;
    if (e >= E) return;
    int s, d;
    if (g_flag) {
        const long long* p = (const long long*)eidx;
        s = (int)p[e];
        d = (int)p[E + e];
    } else {
        const int* p = (const int*)eidx;
        s = p[e];
        d = p[E + e];
    }
    g_edge[e] = make_int2(s, d);
    atomicAdd(&g_deg[d], ew[e]);
    atomicAdd(&g_cnt[d], 1);
}

// ---------------- exclusive scan of g_cnt -> g_rowptr ------------------
__global__ void scan_kernel(int N) {
    __shared__ int sh[32];
    int tid = threadIdx.x;
    int lane = tid & 31, wid = tid >> 5;
    int carry = 0;
    const int CH = 4096;
    for (int base = 0; base < N; base += CH) {
        int idx = base + tid * 4;
        int v0 = (idx + 0 < N) ? g_cnt[idx + 0] : 0;
        int v1 = (idx + 1 < N) ? g_cnt[idx + 1] : 0;
        int v2 = (idx + 2 < N) ? g_cnt[idx + 2] : 0;
        int v3 = (idx + 3 < N) ? g_cnt[idx + 3] : 0;
        int p0 = v0, p1 = p0 + v1, p2 = p1 + v2, p3 = p2 + v3;
        int t = p3;
        #pragma unroll
        for (int o = 1; o < 32; o <<= 1) {
            int u = __shfl_up_sync(0xFFFFFFFFu, t, o);
            if (lane >= o) t += u;
        }
        if (lane == 31) sh[wid] = t;
        __syncthreads();
        if (wid == 0) {
            int s = sh[lane];
            #pragma unroll
            for (int o = 1; o < 32; o <<= 1) {
                int u = __shfl_up_sync(0xFFFFFFFFu, s, o);
                if (lane >= o) s += u;
            }
            sh[lane] = s;
        }
        __syncthreads();
        int woff = (wid > 0) ? sh[wid - 1] : 0;
        int off = carry + woff + (t - p3);
        if (idx + 0 < N) g_rowptr[idx + 0] = off;
        if (idx + 1 < N) g_rowptr[idx + 1] = off + p0;
        if (idx + 2 < N) g_rowptr[idx + 2] = off + p1;
        if (idx + 3 < N) g_rowptr[idx + 3] = off + p2;
        int total = sh[31];
        __syncthreads();
        carry += total;
    }
    if (tid == 0) g_rowptr[N] = carry;
}

// ---------------- pass 2: CSR fill (packed 8B entries) -----------------
__global__ void fill_kernel(const float* __restrict__ ew, int E) {
    int e = blockIdx.x * blockDim.x + threadIdx.x;
    if (e >= E) return;
    int2 ed = g_edge[e];
    float nrm = rsqrtf(g_deg[ed.x]) * ew[e] * rsqrtf(g_deg[ed.y]);
    int pos = g_rowptr[ed.y] + atomicAdd(&g_fill[ed.y], 1);
    g_csr[pos] = make_int2(ed.x, __float_as_int(nrm));
}

// ---------------- fp32 SGEMM: C[N,NOUT] = A[N,K] @ W[K,NOUT] -----------
// BM=128 rows/block, register tile TM x TN, K chunked by 16.
template <int K, int NOUT, int TM, int TN>
__global__ __launch_bounds__((128 / TM) * (NOUT / TN)) void gemm_kernel(
    const float* __restrict__ A, const float* __restrict__ W,
    float* __restrict__ C, int N) {
    constexpr int BM = 128, KC = 16;
    constexpr int NCOL = NOUT / TN;
    constexpr int THREADS = (BM / TM) * NCOL;
    __shared__ __align__(16) float xs[KC][BM];
    __shared__ __align__(16) float ws[KC][NOUT];
    int tid = threadIdx.x;
    int tcol = tid % NCOL, trow = tid / NCOL;
    int r0 = blockIdx.x * BM;

    float acc[TM][TN];
    #pragma unroll
    for (int i = 0; i < TM; i++)
        #pragma unroll
        for (int j = 0; j < TN; j++) acc[i][j] = 0.0f;

    for (int k0 = 0; k0 < K; k0 += KC) {
        // A tile (transposed into xs[kk][row])
        #pragma unroll
        for (int i = tid; i < BM * KC / 4; i += THREADS) {
            int row = i >> 2;
            int kb = (i & 3) * 4;
            float4 u = make_float4(0, 0, 0, 0);
            int g = r0 + row;
            if (g < N)
                u = *(const float4*)(A + (size_t)g * K + k0 + kb);
            xs[kb + 0][row] = u.x; xs[kb + 1][row] = u.y;
            xs[kb + 2][row] = u.z; xs[kb + 3][row] = u.w;
        }
        // W tile
        #pragma unroll
        for (int i = tid; i < KC * NOUT / 4; i += THREADS) {
            int kk = i / (NOUT / 4);
            int c = (i % (NOUT / 4)) * 4;
            *(float4*)&ws[kk][c] =
                *(const float4*)(W + (size_t)(k0 + kk) * NOUT + c);
        }
        __syncthreads();
        #pragma unroll
        for (int kk = 0; kk < KC; kk++) {
            float b[TN], a[TM];
            #pragma unroll
            for (int j = 0; j < TN; j += 4) {
                float4 t = *(float4*)&ws[kk][tcol * TN + j];
                b[j] = t.x; b[j + 1] = t.y; b[j + 2] = t.z; b[j + 3] = t.w;
            }
            #pragma unroll
            for (int i = 0; i < TM; i += 4) {
                float4 t = *(float4*)&xs[kk][trow * TM + i];
                a[i] = t.x; a[i + 1] = t.y; a[i + 2] = t.z; a[i + 3] = t.w;
            }
            #pragma unroll
            for (int i = 0; i < TM; i++)
                #pragma unroll
                for (int j = 0; j < TN; j++)
                    acc[i][j] += a[i] * b[j];
        }
        __syncthreads();
    }
    #pragma unroll
    for (int i = 0; i < TM; i++) {
        int g = r0 + trow * TM + i;
        if (g < N) {
            #pragma unroll
            for (int j = 0; j < TN; j += 4) {
                *(float4*)(C + (size_t)g * NOUT + tcol * TN + j) =
                    make_float4(acc[i][j], acc[i][j + 1],
                                acc[i][j + 2], acc[i][j + 3]);
            }
        }
    }
}

// ---------------- aggregation: out[i] = relu?(sum_e norm*h[src] + self + b)
// one warp per node; packed CSR; 4-deep MLP unroll; optional fused pool.
template <int NF, bool RELU, bool POOL>
__global__ __launch_bounds__(256) void agg_kernel(
    const float* __restrict__ h, const float* __restrict__ bias,
    float* __restrict__ out, int N) {
    int wid = threadIdx.x >> 5;
    int lane = threadIdx.x & 31;
    int node = blockIdx.x * 8 + wid;
    constexpr int FPL = NF / 32;
    float r0 = 0.0f, r1 = 0.0f;

    if (node < N) {
        float di = rsqrtf(g_deg[node]);
        float sw = di * di;
        float acc0, acc1 = 0.0f;
        const float* hrow = h + (size_t)node * NF + lane * FPL;
        if (FPL == 2) {
            float2 v = *(const float2*)hrow;
            acc0 = sw * v.x;
            acc1 = sw * v.y;
        } else {
            acc0 = sw * hrow[0];
        }

        int e = g_rowptr[node];
        int end = g_rowptr[node + 1];
        for (; e + 4 <= end; e += 4) {
            int2 c0 = g_csr[e + 0], c1 = g_csr[e + 1];
            int2 c2 = g_csr[e + 2], c3 = g_csr[e + 3];
            float w0 = __int_as_float(c0.y), w1 = __int_as_float(c1.y);
            float w2 = __int_as_float(c2.y), w3 = __int_as_float(c3.y);
            if (FPL == 2) {
                float2 v0 = *(const float2*)(h + (size_t)c0.x * NF + lane * 2);
                float2 v1 = *(const float2*)(h + (size_t)c1.x * NF + lane * 2);
                float2 v2 = *(const float2*)(h + (size_t)c2.x * NF + lane * 2);
                float2 v3 = *(const float2*)(h + (size_t)c3.x * NF + lane * 2);
                acc0 += w0 * v0.x; acc1 += w0 * v0.y;
                acc0 += w1 * v1.x; acc1 += w1 * v1.y;
                acc0 += w2 * v2.x; acc1 += w2 * v2.y;
                acc0 += w3 * v3.x; acc1 += w3 * v3.y;
            } else {
                float v0 = h[(size_t)c0.x * NF + lane];
                float v1 = h[(size_t)c1.x * NF + lane];
                float v2 = h[(size_t)c2.x * NF + lane];
                float v3 = h[(size_t)c3.x * NF + lane];
                acc0 += w0 * v0 + w1 * v1 + w2 * v2 + w3 * v3;
            }
        }
        for (; e < end; e++) {
            int2 c = g_csr[e];
            float w = __int_as_float(c.y);
            if (FPL == 2) {
                float2 v = *(const float2*)(h + (size_t)c.x * NF + lane * 2);
                acc0 += w * v.x;
                acc1 += w * v.y;
            } else {
                acc0 += w * h[(size_t)c.x * NF + lane];
            }
        }

        if (FPL == 2) {
            r0 = acc0 + bias[lane * 2 + 0];
            r1 = acc1 + bias[lane * 2 + 1];
            if (RELU) { r0 = fmaxf(r0, 0.0f); r1 = fmaxf(r1, 0.0f); }
            *(float2*)(out + (size_t)node * NF + lane * 2) = make_float2(r0, r1);
        } else {
            r0 = acc0 + bias[lane];
            if (RELU) r0 = fmaxf(r0, 0.0f);
            out[(size_t)node * NF + lane] = r0;
        }
    }

    if (POOL) {   // NF==32 path: lane == feature
        __shared__ float shp[8][32];
        shp[wid][lane] = (node < N) ? r0 : 0.0f;
        __syncthreads();
        if (wid == 0) {
            float s = 0.0f;
            #pragma unroll
            for (int j = 0; j < 8; j++) s += shp[j][lane];
            atomicAdd(&g_pool_acc[lane], s);
        }
    }
}

// ---------------- finalize graph embedding -----------------------------
__global__ void pool2_kernel(float* __restrict__ out, int N) {
    int f = threadIdx.x;
    if (f < FOUT)
        out[(size_t)N * FOUT + f] = g_pool_acc[f] / (float)N;
}

// ---------------- fork-join stream context (created at load time) ------
struct StreamCtx {
    cudaStream_t s;
    cudaEvent_t fork, join;
    int ok;
    StreamCtx() : ok(0) {
        if (cudaStreamCreateWithFlags(&s, cudaStreamNonBlocking) == cudaSuccess &&
            cudaEventCreateWithFlags(&fork, cudaEventDisableTiming) == cudaSuccess &&
            cudaEventCreateWithFlags(&join, cudaEventDisableTiming) == cudaSuccess)
            ok = 1;
    }
};
static StreamCtx g_sc;

// ---------------- launch ------------------------------------------------
extern "C" void kernel_launch(void* const* d_in, const int* in_sizes, int n_in,
                              void* d_out, int out_size) {
    const float* x  = (const float*)d_in[0];
    const void*  ei = d_in[1];
    const float* ew = (const float*)d_in[2];
    const float* W1 = (const float*)d_in[3];
    const float* b1 = (const float*)d_in[4];
    const float* W2 = (const float*)d_in[5];
    const float* b2 = (const float*)d_in[6];
    const float* W3 = (const float*)d_in[7];
    const float* b3 = (const float*)d_in[8];
    float* out = (float*)d_out;

    int E = in_sizes[2];
    int N = in_sizes[0] / FIN;
    if (N > MAXN) N = MAXN;
    if (E > MAXE) E = MAXE;

    float *p_ha, *p_hb;
    cudaGetSymbolAddress((void**)&p_ha, g_ha);
    cudaGetSymbolAddress((void**)&p_hb, g_hb);

    int gemm_blocks = cdiv(N, 128);
    int agg_blocks = cdiv(N, 8);
    bool fork = (g_sc.ok == 1);

    // ---- branch A: GEMM1 (independent of graph structure) ----
    if (fork) {
        cudaEventRecord(g_sc.fork, 0);
        cudaStreamWaitEvent(g_sc.s, g_sc.fork, 0);
        gemm_kernel<FIN, HID, 8, 8><<<gemm_blocks, 128, 0, g_sc.s>>>(x, W1, p_ha, N);
        cudaEventRecord(g_sc.join, g_sc.s);
    }

    // ---- branch B: CSR build ----
    setup_kernel<<<cdiv(N, 256), 256>>>((const int*)ei, N);
    edge_pass_kernel<<<cdiv(E, 256), 256>>>(ei, ew, E);
    scan_kernel<<<1, 1024>>>(N);
    fill_kernel<<<cdiv(E, 256), 256>>>(ew, E);

    if (fork)
        cudaStreamWaitEvent(0, g_sc.join, 0);
    else
        gemm_kernel<FIN, HID, 8, 8><<<gemm_blocks, 128>>>(x, W1, p_ha, N);

    // ---- layers ----
    agg_kernel<HID, true, false><<<agg_blocks, 256>>>(p_ha, b1, p_hb, N);
    gemm_kernel<HID, HID, 8, 8><<<gemm_blocks, 128>>>(p_hb, W2, p_ha, N);
    agg_kernel<HID, true, false><<<agg_blocks, 256>>>(p_ha, b2, p_hb, N);
    gemm_kernel<HID, FOUT, 4, 8><<<gemm_blocks, 128>>>(p_hb, W3, p_ha, N);
    agg_kernel<FOUT, false, true><<<agg_blocks, 256>>>(p_ha, b3, out, N);

    if (out_size >= N * FOUT + FOUT)
        pool2_kernel<<<1, 32>>>(out, N);
}

// round 15
// speedup vs baseline: 1.1761x; 1.1079x over previous
#include <cuda_runtime.h>
#include <cstdint>

// ---------------- problem constants (fixed by dataset) ----------------
#define MAXN 100000
#define MAXE 1600000
#define FIN  128
#define HID  64
#define FOUT 32
#define SCAN_TILE 1024
#define MAX_SCAN_BLOCKS ((MAXN + SCAN_TILE - 1) / SCAN_TILE)

// ---------------- device scratch (static: no allocs allowed) ----------
__device__ float g_ha[MAXN * HID];        // GEMM output / agg input
__device__ float g_hb[MAXN * HID];        // agg output (relu'd)
__device__ int2  g_edge[MAXE];            // (src, dst)
__device__ int2  g_csr[MAXE];             // (src, norm-as-bits) packed
__device__ float g_deg[MAXN];
__device__ int   g_cnt[MAXN];
__device__ int   g_fill[MAXN];
__device__ int   g_rowptr[MAXN + 1];
__device__ int   g_bsum[MAX_SCAN_BLOCKS]; // per-block totals
__device__ int   g_boff[MAX_SCAN_BLOCKS]; // exclusive block offsets
__device__ float g_pool_acc[FOUT];
__device__ int   g_flag;                  // 1 if edge_index is int64 layout

static inline int cdiv(int a, int b) { return (a + b - 1) / b; }

// ---------------- setup: init + pool zero + dtype detect --------------
// int64 detection: values < 2^31 nonneg -> every odd int32 word is 0.
__global__ void setup_kernel(const int* __restrict__ ei32, int N) {
    int i = blockIdx.x * blockDim.x + threadIdx.x;
    if (i < N) {
        g_deg[i] = 1.0f;   // self-loop weight
        g_cnt[i] = 0;
        g_fill[i] = 0;
    }
    if (blockIdx.x == 0 && threadIdx.x < 32) {
        g_pool_acc[threadIdx.x] = 0.0f;
        bool z = true;
        #pragma unroll
        for (int j = 0; j < 8; j++)
            z = z && (ei32[2 * (threadIdx.x * 8 + j) + 1] == 0);
        unsigned m = __ballot_sync(0xFFFFFFFFu, z);
        if (threadIdx.x == 0) g_flag = (m == 0xFFFFFFFFu) ? 1 : 0;
    }
}

// ---------------- pass 1: degree + counts + edge conversion -----------
__global__ void edge_pass_kernel(const void* __restrict__ eidx,
                                 const float* __restrict__ ew, int E) {
    int e = blockIdx.x * blockDim.x + threadIdx.x;
    if (e >= E) return;
    int s, d;
    if (g_flag) {
        const long long* p = (const long long*)eidx;
        s = (int)p[e];
        d = (int)p[E + e];
    } else {
        const int* p = (const int*)eidx;
        s = p[e];
        d = p[E + e];
    }
    g_edge[e] = make_int2(s, d);
    atomicAdd(&g_deg[d], ew[e]);
    atomicAdd(&g_cnt[d], 1);
}

// ---------------- phase 1: per-block exclusive scan of g_cnt ----------
__global__ __launch_bounds__(SCAN_TILE) void scan_blocks_kernel(int N) {
    __shared__ int sh[32];
    int tid = threadIdx.x;
    int lane = tid & 31, wid = tid >> 5;
    int idx = blockIdx.x * SCAN_TILE + tid;
    int v = (idx < N) ? g_cnt[idx] : 0;
    // inclusive warp scan
    int t = v;
    #pragma unroll
    for (int o = 1; o < 32; o <<= 1) {
        int u = __shfl_up_sync(0xFFFFFFFFu, t, o);
        if (lane >= o) t += u;
    }
    if (lane == 31) sh[wid] = t;
    __syncthreads();
    if (wid == 0) {
        int s = sh[lane];
        #pragma unroll
        for (int o = 1; o < 32; o <<= 1) {
            int u = __shfl_up_sync(0xFFFFFFFFu, s, o);
            if (lane >= o) s += u;
        }
        sh[lane] = s;
    }
    __syncthreads();
    int woff = (wid > 0) ? sh[wid - 1] : 0;
    if (idx < N) g_rowptr[idx] = woff + t - v;   // exclusive within block
    if (tid == SCAN_TILE - 1) g_bsum[blockIdx.x] = sh[31];
}

// ---------------- phase 2: one warp scans block totals ----------------
__global__ void scan_tops_kernel(int nb, int N) {
    int lane = threadIdx.x;
    int carry = 0;
    for (int base = 0; base < nb; base += 32) {
        int i = base + lane;
        int v = (i < nb) ? g_bsum[i] : 0;
        int t = v;
        #pragma unroll
        for (int o = 1; o < 32; o <<= 1) {
            int u = __shfl_up_sync(0xFFFFFFFFu, t, o);
            if (lane >= o) t += u;
        }
        if (i < nb) g_boff[i] = carry + t - v;   // exclusive
        carry += __shfl_sync(0xFFFFFFFFu, t, 31);
    }
    if (lane == 0) g_rowptr[N] = carry;
}

// ---------------- phase 3: propagate block offsets --------------------
__global__ __launch_bounds__(SCAN_TILE) void scan_add_kernel(int N) {
    int idx = blockIdx.x * SCAN_TILE + threadIdx.x;
    if (idx < N && blockIdx.x > 0) g_rowptr[idx] += g_boff[blockIdx.x];
}

// ---------------- pass 2: CSR fill (packed 8B entries) -----------------
__global__ void fill_kernel(const float* __restrict__ ew, int E) {
    int e = blockIdx.x * blockDim.x + threadIdx.x;
    if (e >= E) return;
    int2 ed = g_edge[e];
    float nrm = rsqrtf(g_deg[ed.x]) * ew[e] * rsqrtf(g_deg[ed.y]);
    int pos = g_rowptr[ed.y] + atomicAdd(&g_fill[ed.y], 1);
    g_csr[pos] = make_int2(ed.x, __float_as_int(nrm));
}

// ---------------- fp32 SGEMM: C[N,NOUT] = A[N,K] @ W[K,NOUT] -----------
// BM=128 rows/block, register tile TM x TN, K chunked by 16.
template <int K, int NOUT, int TM, int TN>
__global__ __launch_bounds__((128 / TM) * (NOUT / TN)) void gemm_kernel(
    const float* __restrict__ A, const float* __restrict__ W,
    float* __restrict__ C, int N) {
    constexpr int BM = 128, KC = 16;
    constexpr int NCOL = NOUT / TN;
    constexpr int THREADS = (BM / TM) * NCOL;
    __shared__ __align__(16) float xs[KC][BM];
    __shared__ __align__(16) float ws[KC][NOUT];
    int tid = threadIdx.x;
    int tcol = tid % NCOL, trow = tid / NCOL;
    int r0 = blockIdx.x * BM;

    float acc[TM][TN];
    #pragma unroll
    for (int i = 0; i < TM; i++)
        #pragma unroll
        for (int j = 0; j < TN; j++) acc[i][j] = 0.0f;

    for (int k0 = 0; k0 < K; k0 += KC) {
        // A tile (transposed into xs[kk][row])
        #pragma unroll
        for (int i = tid; i < BM * KC / 4; i += THREADS) {
            int row = i >> 2;
            int kb = (i & 3) * 4;
            float4 u = make_float4(0, 0, 0, 0);
            int g = r0 + row;
            if (g < N)
                u = *(const float4*)(A + (size_t)g * K + k0 + kb);
            xs[kb + 0][row] = u.x; xs[kb + 1][row] = u.y;
            xs[kb + 2][row] = u.z; xs[kb + 3][row] = u.w;
        }
        // W tile
        #pragma unroll
        for (int i = tid; i < KC * NOUT / 4; i += THREADS) {
            int kk = i / (NOUT / 4);
            int c = (i % (NOUT / 4)) * 4;
            *(float4*)&ws[kk][c] =
                *(const float4*)(W + (size_t)(k0 + kk) * NOUT + c);
        }
        __syncthreads();
        #pragma unroll
        for (int kk = 0; kk < KC; kk++) {
            float b[TN], a[TM];
            #pragma unroll
            for (int j = 0; j < TN; j += 4) {
                float4 t = *(float4*)&ws[kk][tcol * TN + j];
                b[j] = t.x; b[j + 1] = t.y; b[j + 2] = t.z; b[j + 3] = t.w;
            }
            #pragma unroll
            for (int i = 0; i < TM; i += 4) {
                float4 t = *(float4*)&xs[kk][trow * TM + i];
                a[i] = t.x; a[i + 1] = t.y; a[i + 2] = t.z; a[i + 3] = t.w;
            }
            #pragma unroll
            for (int i = 0; i < TM; i++)
                #pragma unroll
                for (int j = 0; j < TN; j++)
                    acc[i][j] += a[i] * b[j];
        }
        __syncthreads();
    }
    #pragma unroll
    for (int i = 0; i < TM; i++) {
        int g = r0 + trow * TM + i;
        if (g < N) {
            #pragma unroll
            for (int j = 0; j < TN; j += 4) {
                *(float4*)(C + (size_t)g * NOUT + tcol * TN + j) =
                    make_float4(acc[i][j], acc[i][j + 1],
                                acc[i][j + 2], acc[i][j + 3]);
            }
        }
    }
}

// ---------------- aggregation: out[i] = relu?(sum_e norm*h[src] + self + b)
// one warp per node; packed CSR; 4-deep MLP unroll; optional fused pool.
template <int NF, bool RELU, bool POOL>
__global__ __launch_bounds__(256) void agg_kernel(
    const float* __restrict__ h, const float* __restrict__ bias,
    float* __restrict__ out, int N) {
    int wid = threadIdx.x >> 5;
    int lane = threadIdx.x & 31;
    int node = blockIdx.x * 8 + wid;
    constexpr int FPL = NF / 32;
    float r0 = 0.0f, r1 = 0.0f;

    if (node < N) {
        float di = rsqrtf(g_deg[node]);
        float sw = di * di;
        float acc0, acc1 = 0.0f;
        const float* hrow = h + (size_t)node * NF + lane * FPL;
        if (FPL == 2) {
            float2 v = *(const float2*)hrow;
            acc0 = sw * v.x;
            acc1 = sw * v.y;
        } else {
            acc0 = sw * hrow[0];
        }

        int e = g_rowptr[node];
        int end = g_rowptr[node + 1];
        for (; e + 4 <= end; e += 4) {
            int2 c0 = g_csr[e + 0], c1 = g_csr[e + 1];
            int2 c2 = g_csr[e + 2], c3 = g_csr[e + 3];
            float w0 = __int_as_float(c0.y), w1 = __int_as_float(c1.y);
            float w2 = __int_as_float(c2.y), w3 = __int_as_float(c3.y);
            if (FPL == 2) {
                float2 v0 = *(const float2*)(h + (size_t)c0.x * NF + lane * 2);
                float2 v1 = *(const float2*)(h + (size_t)c1.x * NF + lane * 2);
                float2 v2 = *(const float2*)(h + (size_t)c2.x * NF + lane * 2);
                float2 v3 = *(const float2*)(h + (size_t)c3.x * NF + lane * 2);
                acc0 += w0 * v0.x; acc1 += w0 * v0.y;
                acc0 += w1 * v1.x; acc1 += w1 * v1.y;
                acc0 += w2 * v2.x; acc1 += w2 * v2.y;
                acc0 += w3 * v3.x; acc1 += w3 * v3.y;
            } else {
                float v0 = h[(size_t)c0.x * NF + lane];
                float v1 = h[(size_t)c1.x * NF + lane];
                float v2 = h[(size_t)c2.x * NF + lane];
                float v3 = h[(size_t)c3.x * NF + lane];
                acc0 += w0 * v0 + w1 * v1 + w2 * v2 + w3 * v3;
            }
        }
        for (; e < end; e++) {
            int2 c = g_csr[e];
            float w = __int_as_float(c.y);
            if (FPL == 2) {
                float2 v = *(const float2*)(h + (size_t)c.x * NF + lane * 2);
                acc0 += w * v.x;
                acc1 += w * v.y;
            } else {
                acc0 += w * h[(size_t)c.x * NF + lane];
            }
        }

        if (FPL == 2) {
            r0 = acc0 + bias[lane * 2 + 0];
            r1 = acc1 + bias[lane * 2 + 1];
            if (RELU) { r0 = fmaxf(r0, 0.0f); r1 = fmaxf(r1, 0.0f); }
            *(float2*)(out + (size_t)node * NF + lane * 2) = make_float2(r0, r1);
        } else {
            r0 = acc0 + bias[lane];
            if (RELU) r0 = fmaxf(r0, 0.0f);
            out[(size_t)node * NF + lane] = r0;
        }
    }

    if (POOL) {   // NF==32 path: lane == feature
        __shared__ float shp[8][32];
        shp[wid][lane] = (node < N) ? r0 : 0.0f;
        __syncthreads();
        if (wid == 0) {
            float s = 0.0f;
            #pragma unroll
            for (int j = 0; j < 8; j++) s += shp[j][lane];
            atomicAdd(&g_pool_acc[lane], s);
        }
    }
}

// ---------------- finalize graph embedding -----------------------------
__global__ void pool2_kernel(float* __restrict__ out, int N) {
    int f = threadIdx.x;
    if (f < FOUT)
        out[(size_t)N * FOUT + f] = g_pool_acc[f] / (float)N;
}

// ---------------- fork-join stream context (created at load time) ------
struct StreamCtx {
    cudaStream_t s;
    cudaEvent_t fork, join;
    int ok;
    StreamCtx() : ok(0) {
        if (cudaStreamCreateWithFlags(&s, cudaStreamNonBlocking) == cudaSuccess &&
            cudaEventCreateWithFlags(&fork, cudaEventDisableTiming) == cudaSuccess &&
            cudaEventCreateWithFlags(&join, cudaEventDisableTiming) == cudaSuccess)
            ok = 1;
    }
};
static StreamCtx g_sc;

// ---------------- launch ------------------------------------------------
extern "C" void kernel_launch(void* const* d_in, const int* in_sizes, int n_in,
                              void* d_out, int out_size) {
    const float* x  = (const float*)d_in[0];
    const void*  ei = d_in[1];
    const float* ew = (const float*)d_in[2];
    const float* W1 = (const float*)d_in[3];
    const float* b1 = (const float*)d_in[4];
    const float* W2 = (const float*)d_in[5];
    const float* b2 = (const float*)d_in[6];
    const float* W3 = (const float*)d_in[7];
    const float* b3 = (const float*)d_in[8];
    float* out = (float*)d_out;

    int E = in_sizes[2];
    int N = in_sizes[0] / FIN;
    if (N > MAXN) N = MAXN;
    if (E > MAXE) E = MAXE;

    float *p_ha, *p_hb;
    cudaGetSymbolAddress((void**)&p_ha, g_ha);
    cudaGetSymbolAddress((void**)&p_hb, g_hb);

    int gemm_blocks = cdiv(N, 128);
    int agg_blocks = cdiv(N, 8);
    int scan_blocks = cdiv(N, SCAN_TILE);
    bool fork = (g_sc.ok == 1);

    // ---- branch A: GEMM1 (independent of graph structure) ----
    if (fork) {
        cudaEventRecord(g_sc.fork, 0);
        cudaStreamWaitEvent(g_sc.s, g_sc.fork, 0);
        gemm_kernel<FIN, HID, 8, 8><<<gemm_blocks, 128, 0, g_sc.s>>>(x, W1, p_ha, N);
        cudaEventRecord(g_sc.join, g_sc.s);
    }

    // ---- branch B: CSR build (parallel 3-phase scan) ----
    setup_kernel<<<cdiv(N, 256), 256>>>((const int*)ei, N);
    edge_pass_kernel<<<cdiv(E, 256), 256>>>(ei, ew, E);
    scan_blocks_kernel<<<scan_blocks, SCAN_TILE>>>(N);
    scan_tops_kernel<<<1, 32>>>(scan_blocks, N);
    scan_add_kernel<<<scan_blocks, SCAN_TILE>>>(N);
    fill_kernel<<<cdiv(E, 256), 256>>>(ew, E);

    if (fork)
        cudaStreamWaitEvent(0, g_sc.join, 0);
    else
        gemm_kernel<FIN, HID, 8, 8><<<gemm_blocks, 128>>>(x, W1, p_ha, N);

    // ---- layers ----
    agg_kernel<HID, true, false><<<agg_blocks, 256>>>(p_ha, b1, p_hb, N);
    gemm_kernel<HID, HID, 8, 8><<<gemm_blocks, 128>>>(p_hb, W2, p_ha, N);
    agg_kernel<HID, true, false><<<agg_blocks, 256>>>(p_ha, b2, p_hb, N);
    gemm_kernel<HID, FOUT, 4, 8><<<gemm_blocks, 128>>>(p_hb, W3, p_ha, N);
    agg_kernel<FOUT, false, true><<<agg_blocks, 256>>>(p_ha, b3, out, N);

    if (out_size >= N * FOUT + FOUT)
        pool2_kernel<<<1, 32>>>(out, N);
}

// round 16
// speedup vs baseline: 1.2250x; 1.0416x over previous
#include <cuda_runtime.h>
#include <cstdint>

// ---------------- problem constants (fixed by dataset) ----------------
#define MAXN 100000
#define MAXE 1600000
#define FIN  128
#define HID  64
#define FOUT 32
#define SCAN_TILE 1024
#define MAX_SCAN_BLOCKS ((MAXN + SCAN_TILE - 1) / SCAN_TILE)

// ---------------- device scratch (static: no allocs allowed) ----------
__device__ float g_ha[MAXN * HID];        // GEMM output / agg input
__device__ float g_hb[MAXN * HID];        // agg output (relu'd)
__device__ int2  g_edge[MAXE];            // (src, dst)
__device__ int2  g_csr[MAXE];             // (src, norm-as-bits) packed
__device__ float g_deg[MAXN];
__device__ int   g_cnt[MAXN];
__device__ int   g_fill[MAXN];
__device__ int   g_rowptr[MAXN + 1];
__device__ int   g_bsum[MAX_SCAN_BLOCKS]; // per-block totals
__device__ int   g_boff[MAX_SCAN_BLOCKS]; // exclusive block offsets
__device__ float g_pool_acc[FOUT];
__device__ int   g_flag;                  // 1 if edge_index is int64 layout

static inline int cdiv(int a, int b) { return (a + b - 1) / b; }

// ---------------- setup: init + pool zero + dtype detect --------------
// int64 detection: values < 2^31 nonneg -> every odd int32 word is 0.
__global__ void setup_kernel(const int* __restrict__ ei32, int N) {
    int i = blockIdx.x * blockDim.x + threadIdx.x;
    if (i < N) {
        g_deg[i] = 1.0f;   // self-loop weight
        g_cnt[i] = 0;
        g_fill[i] = 0;
    }
    if (blockIdx.x == 0 && threadIdx.x < 32) {
        g_pool_acc[threadIdx.x] = 0.0f;
        bool z = true;
        #pragma unroll
        for (int j = 0; j < 8; j++)
            z = z && (ei32[2 * (threadIdx.x * 8 + j) + 1] == 0);
        unsigned m = __ballot_sync(0xFFFFFFFFu, z);
        if (threadIdx.x == 0) g_flag = (m == 0xFFFFFFFFu) ? 1 : 0;
    }
}

// ---------------- pass 1: degree + counts + edge conversion -----------
__global__ void edge_pass_kernel(const void* __restrict__ eidx,
                                 const float* __restrict__ ew, int E) {
    int e = blockIdx.x * blockDim.x + threadIdx.x;
    if (e >= E) return;
    int s, d;
    if (g_flag) {
        const long long* p = (const long long*)eidx;
        s = (int)p[e];
        d = (int)p[E + e];
    } else {
        const int* p = (const int*)eidx;
        s = p[e];
        d = p[E + e];
    }
    g_edge[e] = make_int2(s, d);
    atomicAdd(&g_deg[d], ew[e]);
    atomicAdd(&g_cnt[d], 1);
}

// ---------------- phase 1: per-block exclusive scan of g_cnt ----------
__global__ __launch_bounds__(SCAN_TILE) void scan_blocks_kernel(int N) {
    __shared__ int sh[32];
    int tid = threadIdx.x;
    int lane = tid & 31, wid = tid >> 5;
    int idx = blockIdx.x * SCAN_TILE + tid;
    int v = (idx < N) ? g_cnt[idx] : 0;
    // inclusive warp scan
    int t = v;
    #pragma unroll
    for (int o = 1; o < 32; o <<= 1) {
        int u = __shfl_up_sync(0xFFFFFFFFu, t, o);
        if (lane >= o) t += u;
    }
    if (lane == 31) sh[wid] = t;
    __syncthreads();
    if (wid == 0) {
        int s = sh[lane];
        #pragma unroll
        for (int o = 1; o < 32; o <<= 1) {
            int u = __shfl_up_sync(0xFFFFFFFFu, s, o);
            if (lane >= o) s += u;
        }
        sh[lane] = s;
    }
    __syncthreads();
    int woff = (wid > 0) ? sh[wid - 1] : 0;
    if (idx < N) g_rowptr[idx] = woff + t - v;   // exclusive within block
    if (tid == SCAN_TILE - 1) g_bsum[blockIdx.x] = sh[31];
}

// ---------------- phase 2: one warp scans block totals ----------------
__global__ void scan_tops_kernel(int nb, int N) {
    int lane = threadIdx.x;
    int carry = 0;
    for (int base = 0; base < nb; base += 32) {
        int i = base + lane;
        int v = (i < nb) ? g_bsum[i] : 0;
        int t = v;
        #pragma unroll
        for (int o = 1; o < 32; o <<= 1) {
            int u = __shfl_up_sync(0xFFFFFFFFu, t, o);
            if (lane >= o) t += u;
        }
        if (i < nb) g_boff[i] = carry + t - v;   // exclusive
        carry += __shfl_sync(0xFFFFFFFFu, t, 31);
    }
    if (lane == 0) g_rowptr[N] = carry;
}

// ---------------- phase 3: propagate block offsets --------------------
__global__ __launch_bounds__(SCAN_TILE) void scan_add_kernel(int N) {
    int idx = blockIdx.x * SCAN_TILE + threadIdx.x;
    if (idx < N && blockIdx.x > 0) g_rowptr[idx] += g_boff[blockIdx.x];
}

// ---------------- pass 2: CSR fill (packed 8B entries) -----------------
__global__ void fill_kernel(const float* __restrict__ ew, int E) {
    int e = blockIdx.x * blockDim.x + threadIdx.x;
    if (e >= E) return;
    int2 ed = g_edge[e];
    float nrm = rsqrtf(g_deg[ed.x]) * ew[e] * rsqrtf(g_deg[ed.y]);
    int pos = g_rowptr[ed.y] + atomicAdd(&g_fill[ed.y], 1);
    g_csr[pos] = make_int2(ed.x, __float_as_int(nrm));
}

// ---------------- fp32 SGEMM: C[N,NOUT] = A[N,K] @ W[K,NOUT] -----------
// BM=128 rows/block, register tile TM x TN, K chunked by 16.
template <int K, int NOUT, int TM, int TN>
__global__ __launch_bounds__((128 / TM) * (NOUT / TN)) void gemm_kernel(
    const float* __restrict__ A, const float* __restrict__ W,
    float* __restrict__ C, int N) {
    constexpr int BM = 128, KC = 16;
    constexpr int NCOL = NOUT / TN;
    constexpr int THREADS = (BM / TM) * NCOL;
    __shared__ __align__(16) float xs[KC][BM];
    __shared__ __align__(16) float ws[KC][NOUT];
    int tid = threadIdx.x;
    int tcol = tid % NCOL, trow = tid / NCOL;
    int r0 = blockIdx.x * BM;

    float acc[TM][TN];
    #pragma unroll
    for (int i = 0; i < TM; i++)
        #pragma unroll
        for (int j = 0; j < TN; j++) acc[i][j] = 0.0f;

    for (int k0 = 0; k0 < K; k0 += KC) {
        // A tile (transposed into xs[kk][row])
        #pragma unroll
        for (int i = tid; i < BM * KC / 4; i += THREADS) {
            int row = i >> 2;
            int kb = (i & 3) * 4;
            float4 u = make_float4(0, 0, 0, 0);
            int g = r0 + row;
            if (g < N)
                u = *(const float4*)(A + (size_t)g * K + k0 + kb);
            xs[kb + 0][row] = u.x; xs[kb + 1][row] = u.y;
            xs[kb + 2][row] = u.z; xs[kb + 3][row] = u.w;
        }
        // W tile
        #pragma unroll
        for (int i = tid; i < KC * NOUT / 4; i += THREADS) {
            int kk = i / (NOUT / 4);
            int c = (i % (NOUT / 4)) * 4;
            *(float4*)&ws[kk][c] =
                *(const float4*)(W + (size_t)(k0 + kk) * NOUT + c);
        }
        __syncthreads();
        #pragma unroll
        for (int kk = 0; kk < KC; kk++) {
            float b[TN], a[TM];
            #pragma unroll
            for (int j = 0; j < TN; j += 4) {
                float4 t = *(float4*)&ws[kk][tcol * TN + j];
                b[j] = t.x; b[j + 1] = t.y; b[j + 2] = t.z; b[j + 3] = t.w;
            }
            #pragma unroll
            for (int i = 0; i < TM; i += 4) {
                float4 t = *(float4*)&xs[kk][trow * TM + i];
                a[i] = t.x; a[i + 1] = t.y; a[i + 2] = t.z; a[i + 3] = t.w;
            }
            #pragma unroll
            for (int i = 0; i < TM; i++)
                #pragma unroll
                for (int j = 0; j < TN; j++)
                    acc[i][j] += a[i] * b[j];
        }
        __syncthreads();
    }
    #pragma unroll
    for (int i = 0; i < TM; i++) {
        int g = r0 + trow * TM + i;
        if (g < N) {
            #pragma unroll
            for (int j = 0; j < TN; j += 4) {
                *(float4*)(C + (size_t)g * NOUT + tcol * TN + j) =
                    make_float4(acc[i][j], acc[i][j + 1],
                                acc[i][j + 2], acc[i][j + 3]);
            }
        }
    }
}

// ---------------- aggregation: out[i] = relu?(sum_e norm*h[src] + self + b)
// one warp per node; packed CSR; 4-deep MLP unroll; optional fused pool.
template <int NF, bool RELU, bool POOL>
__global__ __launch_bounds__(256) void agg_kernel(
    const float* __restrict__ h, const float* __restrict__ bias,
    float* __restrict__ out, int N) {
    int wid = threadIdx.x >> 5;
    int lane = threadIdx.x & 31;
    int node = blockIdx.x * 8 + wid;
    constexpr int FPL = NF / 32;
    float r0 = 0.0f, r1 = 0.0f;

    if (node < N) {
        float di = rsqrtf(g_deg[node]);
        float sw = di * di;
        float acc0, acc1 = 0.0f;
        const float* hrow = h + (size_t)node * NF + lane * FPL;
        if (FPL == 2) {
            float2 v = *(const float2*)hrow;
            acc0 = sw * v.x;
            acc1 = sw * v.y;
        } else {
            acc0 = sw * hrow[0];
        }

        int e = g_rowptr[node];
        int end = g_rowptr[node + 1];
        for (; e + 4 <= end; e += 4) {
            int2 c0 = g_csr[e + 0], c1 = g_csr[e + 1];
            int2 c2 = g_csr[e + 2], c3 = g_csr[e + 3];
            float w0 = __int_as_float(c0.y), w1 = __int_as_float(c1.y);
            float w2 = __int_as_float(c2.y), w3 = __int_as_float(c3.y);
            if (FPL == 2) {
                float2 v0 = *(const float2*)(h + (size_t)c0.x * NF + lane * 2);
                float2 v1 = *(const float2*)(h + (size_t)c1.x * NF + lane * 2);
                float2 v2 = *(const float2*)(h + (size_t)c2.x * NF + lane * 2);
                float2 v3 = *(const float2*)(h + (size_t)c3.x * NF + lane * 2);
                acc0 += w0 * v0.x; acc1 += w0 * v0.y;
                acc0 += w1 * v1.x; acc1 += w1 * v1.y;
                acc0 += w2 * v2.x; acc1 += w2 * v2.y;
                acc0 += w3 * v3.x; acc1 += w3 * v3.y;
            } else {
                float v0 = h[(size_t)c0.x * NF + lane];
                float v1 = h[(size_t)c1.x * NF + lane];
                float v2 = h[(size_t)c2.x * NF + lane];
                float v3 = h[(size_t)c3.x * NF + lane];
                acc0 += w0 * v0 + w1 * v1 + w2 * v2 + w3 * v3;
            }
        }
        for (; e < end; e++) {
            int2 c = g_csr[e];
            float w = __int_as_float(c.y);
            if (FPL == 2) {
                float2 v = *(const float2*)(h + (size_t)c.x * NF + lane * 2);
                acc0 += w * v.x;
                acc1 += w * v.y;
            } else {
                acc0 += w * h[(size_t)c.x * NF + lane];
            }
        }

        if (FPL == 2) {
            r0 = acc0 + bias[lane * 2 + 0];
            r1 = acc1 + bias[lane * 2 + 1];
            if (RELU) { r0 = fmaxf(r0, 0.0f); r1 = fmaxf(r1, 0.0f); }
            *(float2*)(out + (size_t)node * NF + lane * 2) = make_float2(r0, r1);
        } else {
            r0 = acc0 + bias[lane];
            if (RELU) r0 = fmaxf(r0, 0.0f);
            out[(size_t)node * NF + lane] = r0;
        }
    }

    if (POOL) {   // NF==32 path: lane == feature
        __shared__ float shp[8][32];
        shp[wid][lane] = (node < N) ? r0 : 0.0f;
        __syncthreads();
        if (wid == 0) {
            float s = 0.0f;
            #pragma unroll
            for (int j = 0; j < 8; j++) s += shp[j][lane];
            atomicAdd(&g_pool_acc[lane], s);
        }
    }
}

// ---------------- finalize graph embedding -----------------------------
__global__ void pool2_kernel(float* __restrict__ out, int N) {
    int f = threadIdx.x;
    if (f < FOUT)
        out[(size_t)N * FOUT + f] = g_pool_acc[f] / (float)N;
}

// ---------------- fork-join stream context (created at load time) ------
struct StreamCtx {
    cudaStream_t s;
    cudaEvent_t fork, join;
    int ok;
    StreamCtx() : ok(0) {
        if (cudaStreamCreateWithFlags(&s, cudaStreamNonBlocking) == cudaSuccess &&
            cudaEventCreateWithFlags(&fork, cudaEventDisableTiming) == cudaSuccess &&
            cudaEventCreateWithFlags(&join, cudaEventDisableTiming) == cudaSuccess)
            ok = 1;
    }
};
static StreamCtx g_sc;

// ---------------- launch ------------------------------------------------
extern "C" void kernel_launch(void* const* d_in, const int* in_sizes, int n_in,
                              void* d_out, int out_size) {
    const float* x  = (const float*)d_in[0];
    const void*  ei = d_in[1];
    const float* ew = (const float*)d_in[2];
    const float* W1 = (const float*)d_in[3];
    const float* b1 = (const float*)d_in[4];
    const float* W2 = (const float*)d_in[5];
    const float* b2 = (const float*)d_in[6];
    const float* W3 = (const float*)d_in[7];
    const float* b3 = (const float*)d_in[8];
    float* out = (float*)d_out;

    int E = in_sizes[2];
    int N = in_sizes[0] / FIN;
    if (N > MAXN) N = MAXN;
    if (E > MAXE) E = MAXE;

    float *p_ha, *p_hb;
    cudaGetSymbolAddress((void**)&p_ha, g_ha);
    cudaGetSymbolAddress((void**)&p_hb, g_hb);

    int gemm_blocks = cdiv(N, 128);
    int agg_blocks = cdiv(N, 8);
    int scan_blocks = cdiv(N, SCAN_TILE);
    bool fork = (g_sc.ok == 1);

    // ---- branch A: GEMM1 (independent of graph structure) ----
    if (fork) {
        cudaEventRecord(g_sc.fork, 0);
        cudaStreamWaitEvent(g_sc.s, g_sc.fork, 0);
        gemm_kernel<FIN, HID, 8, 8><<<gemm_blocks, 128, 0, g_sc.s>>>(x, W1, p_ha, N);
        cudaEventRecord(g_sc.join, g_sc.s);
    }

    // ---- branch B: CSR build (parallel 3-phase scan) ----
    setup_kernel<<<cdiv(N, 256), 256>>>((const int*)ei, N);
    edge_pass_kernel<<<cdiv(E, 256), 256>>>(ei, ew, E);
    scan_blocks_kernel<<<scan_blocks, SCAN_TILE>>>(N);
    scan_tops_kernel<<<1, 32>>>(scan_blocks, N);
    scan_add_kernel<<<scan_blocks, SCAN_TILE>>>(N);
    fill_kernel<<<cdiv(E, 256), 256>>>(ew, E);

    if (fork)
        cudaStreamWaitEvent(0, g_sc.join, 0);
    else
        gemm_kernel<FIN, HID, 8, 8><<<gemm_blocks, 128>>>(x, W1, p_ha, N);

    // ---- layers ----
    agg_kernel<HID, true, false><<<agg_blocks, 256>>>(p_ha, b1, p_hb, N);
    gemm_kernel<HID, HID, 8, 8><<<gemm_blocks, 128>>>(p_hb, W2, p_ha, N);
    agg_kernel<HID, true, false><<<agg_blocks, 256>>>(p_ha, b2, p_hb, N);
    gemm_kernel<HID, FOUT, 4, 8><<<gemm_blocks, 128>>>(p_hb, W3, p_ha, N);
    agg_kernel<FOUT, false, true><<<agg_blocks, 256>>>(p_ha, b3, out, N);

    if (out_size >= N * FOUT + FOUT)
        pool2_kernel<<<1, 32>>>(out, N);
}

// round 17
// speedup vs baseline: 1.2549x; 1.0244x over previous
#include <cuda_runtime.h>
#include <cstdint>

// ---------------- problem constants (fixed by dataset) ----------------
#define MAXN 100000
#define MAXE 1600000
#define FIN  128
#define HID  64
#define FOUT 32
#define SCAN_TILE 1024
#define MAX_SCAN_BLOCKS ((MAXN + SCAN_TILE - 1) / SCAN_TILE)

typedef unsigned long long u64t;

// ---------------- packed f32x2 helpers (sm_103a FFMA2) ----------------
__device__ __forceinline__ void fma2(u64t& acc, u64t a, u64t b) {
    // acc = a * b + acc   (two independent fp32 lanes, IEEE rn each)
    asm("fma.rn.f32x2 %0, %1, %2, %3;" : "=l"(acc) : "l"(a), "l"(b), "l"(acc));
}
__device__ __forceinline__ u64t splat2(float x) {
    u64t r;
    asm("mov.b64 %0, {%1, %1};" : "=l"(r) : "f"(x));
    return r;
}
__device__ __forceinline__ u64t pack2(float lo, float hi) {
    u64t r;
    asm("mov.b64 %0, {%1, %2};" : "=l"(r) : "f"(lo), "f"(hi));
    return r;
}
__device__ __forceinline__ void unpack2(float& lo, float& hi, u64t v) {
    asm("mov.b64 {%0, %1}, %2;" : "=f"(lo), "=f"(hi) : "l"(v));
}

// ---------------- device scratch (static: no allocs allowed) ----------
__device__ float g_ha[MAXN * HID];        // GEMM output / agg input
__device__ float g_hb[MAXN * HID];        // agg output (relu'd)
__device__ int2  g_edge[MAXE];            // (src, dst)
__device__ int2  g_csr[MAXE];             // (src, norm-as-bits) packed
__device__ float g_deg[MAXN];
__device__ int   g_cnt[MAXN];
__device__ int   g_fill[MAXN];
__device__ int   g_rowptr[MAXN + 1];
__device__ int   g_bsum[MAX_SCAN_BLOCKS]; // per-block totals
__device__ float g_pool_acc[FOUT];
__device__ int   g_flag;                  // 1 if edge_index is int64 layout

static inline int cdiv(int a, int b) { return (a + b - 1) / b; }

// ---------------- setup: init + pool zero + dtype detect --------------
// int64 detection: values < 2^31 nonneg -> every odd int32 word is 0.
__global__ void setup_kernel(const int* __restrict__ ei32, int N) {
    int i = blockIdx.x * blockDim.x + threadIdx.x;
    if (i < N) {
        g_deg[i] = 1.0f;   // self-loop weight
        g_cnt[i] = 0;
        g_fill[i] = 0;
    }
    if (blockIdx.x == 0 && threadIdx.x < 32) {
        g_pool_acc[threadIdx.x] = 0.0f;
        bool z = true;
        #pragma unroll
        for (int j = 0; j < 8; j++)
            z = z && (ei32[2 * (threadIdx.x * 8 + j) + 1] == 0);
        unsigned m = __ballot_sync(0xFFFFFFFFu, z);
        if (threadIdx.x == 0) g_flag = (m == 0xFFFFFFFFu) ? 1 : 0;
    }
}

// ---------------- pass 1: degree + counts + edge conversion -----------
__global__ void edge_pass_kernel(const void* __restrict__ eidx,
                                 const float* __restrict__ ew, int E) {
    int e = blockIdx.x * blockDim.x + threadIdx.x;
    if (e >= E) return;
    int s, d;
    if (g_flag) {
        const long long* p = (const long long*)eidx;
        s = (int)p[e];
        d = (int)p[E + e];
    } else {
        const int* p = (const int*)eidx;
        s = p[e];
        d = p[E + e];
    }
    g_edge[e] = make_int2(s, d);
    atomicAdd(&g_deg[d], ew[e]);
    atomicAdd(&g_cnt[d], 1);
}

// ---------------- phase 1: per-block exclusive scan of g_cnt ----------
__global__ __launch_bounds__(SCAN_TILE) void scan_blocks_kernel(int N) {
    __shared__ int sh[32];
    int tid = threadIdx.x;
    int lane = tid & 31, wid = tid >> 5;
    int idx = blockIdx.x * SCAN_TILE + tid;
    int v = (idx < N) ? g_cnt[idx] : 0;
    int t = v;
    #pragma unroll
    for (int o = 1; o < 32; o <<= 1) {
        int u = __shfl_up_sync(0xFFFFFFFFu, t, o);
        if (lane >= o) t += u;
    }
    if (lane == 31) sh[wid] = t;
    __syncthreads();
    if (wid == 0) {
        int s = sh[lane];
        #pragma unroll
        for (int o = 1; o < 32; o <<= 1) {
            int u = __shfl_up_sync(0xFFFFFFFFu, s, o);
            if (lane >= o) s += u;
        }
        sh[lane] = s;
    }
    __syncthreads();
    int woff = (wid > 0) ? sh[wid - 1] : 0;
    if (idx < N) g_rowptr[idx] = woff + t - v;   // exclusive within block
    if (tid == SCAN_TILE - 1) g_bsum[blockIdx.x] = sh[31];
}

// ---------------- phase 2+3 fused: block offset reduce + propagate ----
__global__ __launch_bounds__(SCAN_TILE) void scan_finish_kernel(int nb, int N) {
    __shared__ int sred[32];
    __shared__ int s_off;
    int tid = threadIdx.x;
    int lane = tid & 31, wid = tid >> 5;
    // reduce g_bsum[0..blockIdx.x) with the first 4 warps
    int v = 0;
    if (tid < 128 && tid < blockIdx.x) v = g_bsum[tid];
    #pragma unroll
    for (int o = 16; o > 0; o >>= 1)
        v += __shfl_down_sync(0xFFFFFFFFu, v, o);
    if (lane == 0 && wid < 4) sred[wid] = v;
    __syncthreads();
    if (tid == 0) {
        int off = sred[0] + sred[1] + sred[2] + sred[3];
        s_off = off;
        if (blockIdx.x == (unsigned)(nb - 1))
            g_rowptr[N] = off + g_bsum[blockIdx.x];
    }
    __syncthreads();
    int off = s_off;
    int idx = blockIdx.x * SCAN_TILE + tid;
    if (idx < N && off != 0) g_rowptr[idx] += off;
}

// ---------------- pass 2: CSR fill (packed 8B entries) -----------------
__global__ void fill_kernel(const float* __restrict__ ew, int E) {
    int e = blockIdx.x * blockDim.x + threadIdx.x;
    if (e >= E) return;
    int2 ed = g_edge[e];
    float nrm = rsqrtf(g_deg[ed.x]) * ew[e] * rsqrtf(g_deg[ed.y]);
    int pos = g_rowptr[ed.y] + atomicAdd(&g_fill[ed.y], 1);
    g_csr[pos] = make_int2(ed.x, __float_as_int(nrm));
}

// ---------------- fp32 SGEMM: C[N,NOUT] = A[N,K] @ W[K,NOUT] -----------
// BM=128 rows/block, register tile TM x TN, K chunked by 16.
// Inner product uses packed fma.rn.f32x2 (2 fp32 FMAs per fma-pipe slot).
template <int K, int NOUT, int TM, int TN>
__global__ __launch_bounds__((128 / TM) * (NOUT / TN)) void gemm_kernel(
    const float* __restrict__ A, const float* __restrict__ W,
    float* __restrict__ C, int N) {
    constexpr int BM = 128, KC = 16;
    constexpr int NCOL = NOUT / TN;
    constexpr int THREADS = (BM / TM) * NCOL;
    constexpr int TP = TN / 2;          // packed pairs per row
    __shared__ __align__(16) float xs[KC][BM];
    __shared__ __align__(16) float ws[KC][NOUT];
    int tid = threadIdx.x;
    int tcol = tid % NCOL, trow = tid / NCOL;
    int r0 = blockIdx.x * BM;

    u64t acc2[TM][TP];
    #pragma unroll
    for (int i = 0; i < TM; i++)
        #pragma unroll
        for (int j = 0; j < TP; j++) acc2[i][j] = 0ULL;

    for (int k0 = 0; k0 < K; k0 += KC) {
        // A tile (transposed into xs[kk][row])
        #pragma unroll
        for (int i = tid; i < BM * KC / 4; i += THREADS) {
            int row = i >> 2;
            int kb = (i & 3) * 4;
            float4 u = make_float4(0, 0, 0, 0);
            int g = r0 + row;
            if (g < N)
                u = *(const float4*)(A + (size_t)g * K + k0 + kb);
            xs[kb + 0][row] = u.x; xs[kb + 1][row] = u.y;
            xs[kb + 2][row] = u.z; xs[kb + 3][row] = u.w;
        }
        // W tile
        #pragma unroll
        for (int i = tid; i < KC * NOUT / 4; i += THREADS) {
            int kk = i / (NOUT / 4);
            int c = (i % (NOUT / 4)) * 4;
            *(float4*)&ws[kk][c] =
                *(const float4*)(W + (size_t)(k0 + kk) * NOUT + c);
        }
        __syncthreads();
        #pragma unroll
        for (int kk = 0; kk < KC; kk++) {
            u64t b2[TP];
            const u64t* bp = (const u64t*)&ws[kk][tcol * TN];
            #pragma unroll
            for (int j = 0; j < TP; j++) b2[j] = bp[j];
            float a[TM];
            #pragma unroll
            for (int i = 0; i < TM; i += 4) {
                float4 t = *(float4*)&xs[kk][trow * TM + i];
                a[i] = t.x; a[i + 1] = t.y; a[i + 2] = t.z; a[i + 3] = t.w;
            }
            #pragma unroll
            for (int i = 0; i < TM; i++) {
                u64t a2 = splat2(a[i]);
                #pragma unroll
                for (int j = 0; j < TP; j++)
                    fma2(acc2[i][j], a2, b2[j]);
            }
        }
        __syncthreads();
    }
    #pragma unroll
    for (int i = 0; i < TM; i++) {
        int g = r0 + trow * TM + i;
        if (g < N) {
            #pragma unroll
            for (int j = 0; j < TP; j += 2) {
                float4 o;
                unpack2(o.x, o.y, acc2[i][j]);
                unpack2(o.z, o.w, acc2[i][j + 1]);
                *(float4*)(C + (size_t)g * NOUT + tcol * TN + j * 2) = o;
            }
        }
    }
}

// ---------------- aggregation: out[i] = relu?(sum_e norm*h[src] + self + b)
// one warp per node; packed CSR; 4-deep MLP unroll; f32x2 accumulate.
template <int NF, bool RELU, bool POOL>
__global__ __launch_bounds__(256) void agg_kernel(
    const float* __restrict__ h, const float* __restrict__ bias,
    float* __restrict__ out, int N) {
    int wid = threadIdx.x >> 5;
    int lane = threadIdx.x & 31;
    int node = blockIdx.x * 8 + wid;
    constexpr int FPL = NF / 32;
    float r0 = 0.0f, r1 = 0.0f;

    if (node < N) {
        float di = rsqrtf(g_deg[node]);
        float sw = di * di;
        int e = g_rowptr[node];
        int end = g_rowptr[node + 1];

        if (FPL == 2) {
            const u64t* hp = (const u64t*)h;   // 8B rows of 2 feats
            int stride = NF / 2;
            float2 v = *(const float2*)(h + (size_t)node * NF + lane * 2);
            u64t acc2 = pack2(sw * v.x, sw * v.y);
            for (; e + 4 <= end; e += 4) {
                int2 c0 = g_csr[e + 0], c1 = g_csr[e + 1];
                int2 c2 = g_csr[e + 2], c3 = g_csr[e + 3];
                u64t v0 = hp[(size_t)c0.x * stride + lane];
                u64t v1 = hp[(size_t)c1.x * stride + lane];
                u64t v2 = hp[(size_t)c2.x * stride + lane];
                u64t v3 = hp[(size_t)c3.x * stride + lane];
                fma2(acc2, splat2(__int_as_float(c0.y)), v0);
                fma2(acc2, splat2(__int_as_float(c1.y)), v1);
                fma2(acc2, splat2(__int_as_float(c2.y)), v2);
                fma2(acc2, splat2(__int_as_float(c3.y)), v3);
            }
            for (; e < end; e++) {
                int2 c = g_csr[e];
                fma2(acc2, splat2(__int_as_float(c.y)),
                     hp[(size_t)c.x * stride + lane]);
            }
            float acc0, acc1;
            unpack2(acc0, acc1, acc2);
            r0 = acc0 + bias[lane * 2 + 0];
            r1 = acc1 + bias[lane * 2 + 1];
            if (RELU) { r0 = fmaxf(r0, 0.0f); r1 = fmaxf(r1, 0.0f); }
            *(float2*)(out + (size_t)node * NF + lane * 2) = make_float2(r0, r1);
        } else {
            float acc0 = sw * h[(size_t)node * NF + lane];
            for (; e + 4 <= end; e += 4) {
                int2 c0 = g_csr[e + 0], c1 = g_csr[e + 1];
                int2 c2 = g_csr[e + 2], c3 = g_csr[e + 3];
                float v0 = h[(size_t)c0.x * NF + lane];
                float v1 = h[(size_t)c1.x * NF + lane];
                float v2 = h[(size_t)c2.x * NF + lane];
                float v3 = h[(size_t)c3.x * NF + lane];
                acc0 += __int_as_float(c0.y) * v0 + __int_as_float(c1.y) * v1 +
                        __int_as_float(c2.y) * v2 + __int_as_float(c3.y) * v3;
            }
            for (; e < end; e++) {
                int2 c = g_csr[e];
                acc0 += __int_as_float(c.y) * h[(size_t)c.x * NF + lane];
            }
            r0 = acc0 + bias[lane];
            if (RELU) r0 = fmaxf(r0, 0.0f);
            out[(size_t)node * NF + lane] = r0;
        }
    }

    if (POOL) {   // NF==32 path: lane == feature
        __shared__ float shp[8][32];
        shp[wid][lane] = (node < N) ? r0 : 0.0f;
        __syncthreads();
        if (wid == 0) {
            float s = 0.0f;
            #pragma unroll
            for (int j = 0; j < 8; j++) s += shp[j][lane];
            atomicAdd(&g_pool_acc[lane], s);
        }
    }
}

// ---------------- finalize graph embedding -----------------------------
__global__ void pool2_kernel(float* __restrict__ out, int N) {
    int f = threadIdx.x;
    if (f < FOUT)
        out[(size_t)N * FOUT + f] = g_pool_acc[f] / (float)N;
}

// ---------------- fork-join stream context (created at load time) ------
struct StreamCtx {
    cudaStream_t s;
    cudaEvent_t fork, join;
    int ok;
    StreamCtx() : ok(0) {
        if (cudaStreamCreateWithFlags(&s, cudaStreamNonBlocking) == cudaSuccess &&
            cudaEventCreateWithFlags(&fork, cudaEventDisableTiming) == cudaSuccess &&
            cudaEventCreateWithFlags(&join, cudaEventDisableTiming) == cudaSuccess)
            ok = 1;
    }
};
static StreamCtx g_sc;

// ---------------- launch ------------------------------------------------
extern "C" void kernel_launch(void* const* d_in, const int* in_sizes, int n_in,
                              void* d_out, int out_size) {
    const float* x  = (const float*)d_in[0];
    const void*  ei = d_in[1];
    const float* ew = (const float*)d_in[2];
    const float* W1 = (const float*)d_in[3];
    const float* b1 = (const float*)d_in[4];
    const float* W2 = (const float*)d_in[5];
    const float* b2 = (const float*)d_in[6];
    const float* W3 = (const float*)d_in[7];
    const float* b3 = (const float*)d_in[8];
    float* out = (float*)d_out;

    int E = in_sizes[2];
    int N = in_sizes[0] / FIN;
    if (N > MAXN) N = MAXN;
    if (E > MAXE) E = MAXE;

    float *p_ha, *p_hb;
    cudaGetSymbolAddress((void**)&p_ha, g_ha);
    cudaGetSymbolAddress((void**)&p_hb, g_hb);

    int gemm_blocks = cdiv(N, 128);
    int agg_blocks = cdiv(N, 8);
    int scan_blocks = cdiv(N, SCAN_TILE);
    bool fork = (g_sc.ok == 1);

    // ---- branch A: GEMM1 (independent of graph structure) ----
    if (fork) {
        cudaEventRecord(g_sc.fork, 0);
        cudaStreamWaitEvent(g_sc.s, g_sc.fork, 0);
        gemm_kernel<FIN, HID, 8, 8><<<gemm_blocks, 128, 0, g_sc.s>>>(x, W1, p_ha, N);
        cudaEventRecord(g_sc.join, g_sc.s);
    }

    // ---- branch B: CSR build (parallel scan, 2 kernels) ----
    setup_kernel<<<cdiv(N, 256), 256>>>((const int*)ei, N);
    edge_pass_kernel<<<cdiv(E, 256), 256>>>(ei, ew, E);
    scan_blocks_kernel<<<scan_blocks, SCAN_TILE>>>(N);
    scan_finish_kernel<<<scan_blocks, SCAN_TILE>>>(scan_blocks, N);
    fill_kernel<<<cdiv(E, 256), 256>>>(ew, E);

    if (fork)
        cudaStreamWaitEvent(0, g_sc.join, 0);
    else
        gemm_kernel<FIN, HID, 8, 8><<<gemm_blocks, 128>>>(x, W1, p_ha, N);

    // ---- layers ----
    agg_kernel<HID, true, false><<<agg_blocks, 256>>>(p_ha, b1, p_hb, N);
    gemm_kernel<HID, HID, 8, 8><<<gemm_blocks, 128>>>(p_hb, W2, p_ha, N);
    agg_kernel<HID, true, false><<<agg_blocks, 256>>>(p_ha, b2, p_hb, N);
    gemm_kernel<HID, FOUT, 4, 8><<<gemm_blocks, 128>>>(p_hb, W3, p_ha, N);
    agg_kernel<FOUT, false, true><<<agg_blocks, 256>>>(p_ha, b3, out, N);

    if (out_size >= N * FOUT + FOUT)
        pool2_kernel<<<1, 32>>>(out, N);
}